// round 10
// baseline (speedup 1.0000x reference)
#include <cuda_runtime.h>
#include <cuda_bf16.h>
#include <mma.h>
#include <cstdint>
#include <math.h>

using namespace nvcuda;

#define BTCH 2
#define SEQ  2048
#define DIM  1024
#define NH   16
#define HDM  64
#define NTOK (BTCH*SEQ)

// ---------------- device global scratch (no allocs allowed) ----------------
__device__ float g_q[NTOK*DIM];
__device__ float g_k[NTOK*DIM];
__device__ float g_v[NTOK*DIM];
// bf16 hi/lo splits: 3 activation inputs, 4 weights, attention output
__device__ __nv_bfloat16 g_i0h[NTOK*DIM], g_i0l[NTOK*DIM];
__device__ __nv_bfloat16 g_i1h[NTOK*DIM], g_i1l[NTOK*DIM];
__device__ __nv_bfloat16 g_i2h[NTOK*DIM], g_i2l[NTOK*DIM];
__device__ __nv_bfloat16 g_w0h[DIM*DIM], g_w0l[DIM*DIM];
__device__ __nv_bfloat16 g_w1h[DIM*DIM], g_w1l[DIM*DIM];
__device__ __nv_bfloat16 g_w2h[DIM*DIM], g_w2l[DIM*DIM];
__device__ __nv_bfloat16 g_w3h[DIM*DIM], g_w3l[DIM*DIM];
__device__ __nv_bfloat16 g_ath[NTOK*DIM], g_atl[NTOK*DIM];

__device__ __forceinline__ uint2 pack4_bf16(float a, float b, float c, float d) {
    __nv_bfloat162 lo = __floats2bfloat162_rn(a, b);
    __nv_bfloat162 hi = __floats2bfloat162_rn(c, d);
    uint2 r;
    r.x = *reinterpret_cast<uint32_t*>(&lo);
    r.y = *reinterpret_cast<uint32_t*>(&hi);
    return r;
}

__device__ __forceinline__ void cp16(uint32_t dst, const void* src) {
    asm volatile("cp.async.cg.shared.global [%0], [%1], 16;"
                 :: "r"(dst), "l"(src) : "memory");
}
__device__ __forceinline__ void cp_commit() {
    asm volatile("cp.async.commit_group;" ::: "memory");
}
__device__ __forceinline__ void cp_wait1() {
    asm volatile("cp.async.wait_group 1;" ::: "memory");
}
__device__ __forceinline__ void cp_wait0() {
    asm volatile("cp.async.wait_group 0;" ::: "memory");
}

// ---------------------------------------------------------------------------
// fp32 -> bf16 hi/lo split, 4 elements/thread. Up to 4 tensors via grid.z.
// ---------------------------------------------------------------------------
struct Split4 {
    const float* s[4];
    __nv_bfloat16* h[4];
    __nv_bfloat16* l[4];
};
__global__ void splitk(Split4 a) {
    int z = blockIdx.z;
    size_t i = ((size_t)blockIdx.x * blockDim.x + threadIdx.x) * 4;
    float4 v = *(const float4*)(a.s[z] + i);
    float hx = __bfloat162float(__float2bfloat16(v.x));
    float hy = __bfloat162float(__float2bfloat16(v.y));
    float hz = __bfloat162float(__float2bfloat16(v.z));
    float hw = __bfloat162float(__float2bfloat16(v.w));
    *(uint2*)(a.h[z] + i) = pack4_bf16(hx, hy, hz, hw);
    *(uint2*)(a.l[z] + i) = pack4_bf16(v.x - hx, v.y - hy, v.z - hz, v.w - hw);
}

// ---------------------------------------------------------------------------
// bf16 WMMA GEMM + bias, 3x compensation, cp.async double buffer.
//   C[M,N] = (Ah+Al)[M,K] @ (Wh+Wl)[K,N] + bias  (dropping Al*Wl)
// CTA 128x128, BK=32, 256 thr = 8 warps (4M x 2N), warp tile 32x64.
// Up to 3 independent GEMMs via grid.z.
// smem per stage: Ah[128][48] Al[128][48] Bh[32][136] Bl[32][136] = 41984B
// 2 stages + bias(16x128 f32) = 92160B dynamic.
// ---------------------------------------------------------------------------
struct GemmArgs {
    const __nv_bfloat16 *ah[3], *al[3], *wh[3], *wl[3];
    const float* bias[3];
    float* c[3];
};

#define STAGE_BYTES 41984
#define OFF_AL 12288
#define OFF_BH 24576
#define OFF_BL 33280
#define GEMM_SMEM (2*STAGE_BYTES + 8192)

__global__ __launch_bounds__(256, 2)
void gemm_bf3(GemmArgs g) {
    extern __shared__ __align__(16) char sm[];
    int z = blockIdx.z;
    const __nv_bfloat16* Ahg = g.ah[z];
    const __nv_bfloat16* Alg = g.al[z];
    const __nv_bfloat16* Whg = g.wh[z];
    const __nv_bfloat16* Wlg = g.wl[z];
    const float* bias = g.bias[z];
    float* C = g.c[z];

    int tid  = threadIdx.x;
    int warp = tid >> 5;
    int wm   = warp >> 1;          // 0..3
    int wn   = warp & 1;           // 0..1
    int m0 = blockIdx.y * 128;
    int n0 = blockIdx.x * 128;

    uint32_t sbase = (uint32_t)__cvta_generic_to_shared(sm);
    float* biasS = (float*)(sm + 2 * STAGE_BYTES);

    // issue one stage of cp.async loads for chunk c into stage st
    auto stage_load = [&](int st, int c) {
        uint32_t b = sbase + st * STAGE_BYTES;
        #pragma unroll
        for (int r = 0; r < 2; r++) {
            int id = r * 256 + tid;          // 0..511
            int row = id >> 2, c4 = id & 3;  // A: 128 rows x 4 chunks
            size_t off = (size_t)(m0 + row) * DIM + c * 32 + c4 * 8;
            cp16(b + row * 96 + c4 * 16, Ahg + off);
            cp16(b + OFF_AL + row * 96 + c4 * 16, Alg + off);
        }
        #pragma unroll
        for (int r = 0; r < 2; r++) {
            int id = r * 256 + tid;
            int row = id >> 4, c4 = id & 15; // B: 32 rows x 16 chunks
            size_t off = (size_t)(c * 32 + row) * DIM + n0 + c4 * 8;
            cp16(b + OFF_BH + row * 272 + c4 * 16, Whg + off);
            cp16(b + OFF_BL + row * 272 + c4 * 16, Wlg + off);
        }
    };

    // bias tile (16 replicated rows)
    for (int i = tid; i < 16 * 128; i += 256)
        biasS[i] = bias[n0 + (i & 127)];

    stage_load(0, 0);
    cp_commit();
    __syncthreads();   // biasS ready

    wmma::fragment<wmma::accumulator, 16, 16, 16, float> acc[2][4];
    #pragma unroll
    for (int mi = 0; mi < 2; mi++)
        #pragma unroll
        for (int ni = 0; ni < 4; ni++)
            wmma::load_matrix_sync(acc[mi][ni], biasS + wn * 64 + ni * 16,
                                   128, wmma::mem_row_major);

    for (int c = 0; c < 32; c++) {
        if (c < 31) {
            stage_load((c + 1) & 1, c + 1);
            cp_commit();
            cp_wait1();
        } else {
            cp_wait0();
        }
        __syncthreads();

        const char* sb = sm + (c & 1) * STAGE_BYTES;
        const __nv_bfloat16* sAh = (const __nv_bfloat16*)sb;
        const __nv_bfloat16* sAl = (const __nv_bfloat16*)(sb + OFF_AL);
        const __nv_bfloat16* sBh = (const __nv_bfloat16*)(sb + OFF_BH);
        const __nv_bfloat16* sBl = (const __nv_bfloat16*)(sb + OFF_BL);

        #pragma unroll
        for (int kk = 0; kk < 2; kk++) {
            wmma::fragment<wmma::matrix_a, 16, 16, 16, __nv_bfloat16, wmma::row_major> ah[2], al[2];
            #pragma unroll
            for (int mi = 0; mi < 2; mi++) {
                wmma::load_matrix_sync(ah[mi], sAh + (wm*32 + mi*16) * 48 + kk*16, 48);
                wmma::load_matrix_sync(al[mi], sAl + (wm*32 + mi*16) * 48 + kk*16, 48);
            }
            #pragma unroll
            for (int ni = 0; ni < 4; ni++) {
                wmma::fragment<wmma::matrix_b, 16, 16, 16, __nv_bfloat16, wmma::row_major> bh, bl;
                wmma::load_matrix_sync(bh, sBh + (kk*16) * 136 + wn*64 + ni*16, 136);
                wmma::load_matrix_sync(bl, sBl + (kk*16) * 136 + wn*64 + ni*16, 136);
                #pragma unroll
                for (int mi = 0; mi < 2; mi++) {
                    wmma::mma_sync(acc[mi][ni], ah[mi], bh, acc[mi][ni]);
                    wmma::mma_sync(acc[mi][ni], ah[mi], bl, acc[mi][ni]);
                    wmma::mma_sync(acc[mi][ni], al[mi], bh, acc[mi][ni]);
                }
            }
        }
        __syncthreads();
    }

    #pragma unroll
    for (int mi = 0; mi < 2; mi++)
        #pragma unroll
        for (int ni = 0; ni < 4; ni++)
            wmma::store_matrix_sync(
                C + (size_t)(m0 + wm*32 + mi*16) * DIM + n0 + wn*64 + ni*16,
                acc[mi][ni], DIM, wmma::mem_row_major);
}

// ---------------------------------------------------------------------------
// Flash attention, fp32 compute (unchanged math); epilogue emits bf16 hi/lo.
// ---------------------------------------------------------------------------
__global__ __launch_bounds__(256, 4)
void flash_attn(const float* __restrict__ Qg, const float* __restrict__ Kg,
                const float* __restrict__ Vg,
                __nv_bfloat16* __restrict__ Oh, __nv_bfloat16* __restrict__ Ol) {
    __shared__ float Qs[64][64];
    __shared__ float KsPs[64*64];
    __shared__ float Vs[64][64];

    int tid = threadIdx.x;
    int ty = tid >> 4, tx = tid & 15;
    int bh = blockIdx.y;
    int b = bh / NH, h = bh % NH;
    int q0 = blockIdx.x * 64;

    const float scale = 0.125f;

    {
        const float* Qp = Qg + (size_t)(b*SEQ + q0) * DIM + h*HDM;
        #pragma unroll
        for (int it = 0; it < 4; it++) {
            int idx4 = tid + it * 256;
            int r = idx4 >> 4;
            int cc = (idx4 & 15) * 4;
            float4 v = *(const float4*)&Qp[(size_t)r * DIM + cc];
            Qs[cc+0][r] = v.x; Qs[cc+1][r] = v.y;
            Qs[cc+2][r] = v.z; Qs[cc+3][r] = v.w;
        }
    }

    float o[4][4];
    float m_i[4], l_i[4];
    #pragma unroll
    for (int i = 0; i < 4; i++) {
        m_i[i] = -1e30f; l_i[i] = 0.f;
        #pragma unroll
        for (int j = 0; j < 4; j++) o[i][j] = 0.f;
    }

    for (int k0 = 0; k0 < SEQ; k0 += 64) {
        __syncthreads();
        {
            const float* Kp = Kg + (size_t)(b*SEQ + k0) * DIM + h*HDM;
            const float* Vp = Vg + (size_t)(b*SEQ + k0) * DIM + h*HDM;
            #pragma unroll
            for (int it = 0; it < 4; it++) {
                int idx4 = tid + it * 256;
                int r = idx4 >> 4;
                int cc = (idx4 & 15) * 4;
                float4 vk = *(const float4*)&Kp[(size_t)r * DIM + cc];
                KsPs[(cc+0)*64 + r] = vk.x; KsPs[(cc+1)*64 + r] = vk.y;
                KsPs[(cc+2)*64 + r] = vk.z; KsPs[(cc+3)*64 + r] = vk.w;
                float4 vv = *(const float4*)&Vp[(size_t)r * DIM + cc];
                *(float4*)&Vs[r][cc] = vv;
            }
        }
        __syncthreads();

        float s[4][4];
        #pragma unroll
        for (int i = 0; i < 4; i++)
            #pragma unroll
            for (int j = 0; j < 4; j++) s[i][j] = 0.f;

        #pragma unroll 8
        for (int kk = 0; kk < 64; kk++) {
            float4 q4 = *(float4*)&Qs[kk][ty*4];
            float4 k4 = *(float4*)&KsPs[kk*64 + tx*4];
            float qv[4] = {q4.x, q4.y, q4.z, q4.w};
            float kv[4] = {k4.x, k4.y, k4.z, k4.w};
            #pragma unroll
            for (int i = 0; i < 4; i++)
                #pragma unroll
                for (int j = 0; j < 4; j++)
                    s[i][j] += qv[i] * kv[j];
        }

        #pragma unroll
        for (int i = 0; i < 4; i++) {
            float tm = s[i][0] * scale;
            #pragma unroll
            for (int j = 1; j < 4; j++) tm = fmaxf(tm, s[i][j] * scale);
            #pragma unroll
            for (int d = 1; d < 16; d <<= 1)
                tm = fmaxf(tm, __shfl_xor_sync(0xffffffffu, tm, d));
            float mnew = fmaxf(m_i[i], tm);
            float corr = __expf(m_i[i] - mnew);
            m_i[i] = mnew;
            float rs = 0.f;
            #pragma unroll
            for (int j = 0; j < 4; j++) {
                float p = __expf(s[i][j] * scale - mnew);
                s[i][j] = p;
                rs += p;
            }
            #pragma unroll
            for (int d = 1; d < 16; d <<= 1)
                rs += __shfl_xor_sync(0xffffffffu, rs, d);
            l_i[i] = l_i[i] * corr + rs;
            #pragma unroll
            for (int j = 0; j < 4; j++) o[i][j] *= corr;
        }

        __syncthreads();
        #pragma unroll
        for (int i = 0; i < 4; i++) {
            float4 pv = make_float4(s[i][0], s[i][1], s[i][2], s[i][3]);
            *(float4*)&KsPs[(ty*4 + i)*64 + tx*4] = pv;
        }
        __syncthreads();

        #pragma unroll 8
        for (int kk = 0; kk < 64; kk++) {
            float4 v4 = *(float4*)&Vs[kk][tx*4];
            float vv[4] = {v4.x, v4.y, v4.z, v4.w};
            #pragma unroll
            for (int i = 0; i < 4; i++) {
                float p = KsPs[(ty*4 + i)*64 + kk];
                #pragma unroll
                for (int j = 0; j < 4; j++)
                    o[i][j] += p * vv[j];
            }
        }
    }

    #pragma unroll
    for (int i = 0; i < 4; i++) {
        float inv = 1.f / l_i[i];
        int row = b*SEQ + q0 + ty*4 + i;
        size_t base = (size_t)row * DIM + h*HDM + tx*4;
        float rx = o[i][0]*inv, ry = o[i][1]*inv, rz = o[i][2]*inv, rw = o[i][3]*inv;
        float hx = __bfloat162float(__float2bfloat16(rx));
        float hy = __bfloat162float(__float2bfloat16(ry));
        float hz = __bfloat162float(__float2bfloat16(rz));
        float hw = __bfloat162float(__float2bfloat16(rw));
        *(uint2*)&Oh[base] = pack4_bf16(hx, hy, hz, hw);
        *(uint2*)&Ol[base] = pack4_bf16(rx - hx, ry - hy, rz - hz, rw - hw);
    }
}

extern "C" void kernel_launch(void* const* d_in, const int* in_sizes, int n_in,
                              void* d_out, int out_size) {
    const float* query = (const float*)d_in[0];
    const float* key   = (const float*)d_in[1];
    const float* value = (const float*)d_in[2];
    const float* Wq = (const float*)d_in[3];
    const float* bq = (const float*)d_in[4];
    const float* Wk = (const float*)d_in[5];
    const float* bk = (const float*)d_in[6];
    const float* Wv = (const float*)d_in[7];
    const float* bv = (const float*)d_in[8];
    const float* Wo = (const float*)d_in[9];
    const float* bo = (const float*)d_in[10];
    float* out = (float*)d_out;

    float *gq, *gk, *gv;
    __nv_bfloat16 *i0h,*i0l,*i1h,*i1l,*i2h,*i2l;
    __nv_bfloat16 *w0h,*w0l,*w1h,*w1l,*w2h,*w2l,*w3h,*w3l,*ath,*atl;
    cudaGetSymbolAddress((void**)&gq, g_q);
    cudaGetSymbolAddress((void**)&gk, g_k);
    cudaGetSymbolAddress((void**)&gv, g_v);
    cudaGetSymbolAddress((void**)&i0h, g_i0h); cudaGetSymbolAddress((void**)&i0l, g_i0l);
    cudaGetSymbolAddress((void**)&i1h, g_i1h); cudaGetSymbolAddress((void**)&i1l, g_i1l);
    cudaGetSymbolAddress((void**)&i2h, g_i2h); cudaGetSymbolAddress((void**)&i2l, g_i2l);
    cudaGetSymbolAddress((void**)&w0h, g_w0h); cudaGetSymbolAddress((void**)&w0l, g_w0l);
    cudaGetSymbolAddress((void**)&w1h, g_w1h); cudaGetSymbolAddress((void**)&w1l, g_w1l);
    cudaGetSymbolAddress((void**)&w2h, g_w2h); cudaGetSymbolAddress((void**)&w2l, g_w2l);
    cudaGetSymbolAddress((void**)&w3h, g_w3h); cudaGetSymbolAddress((void**)&w3l, g_w3l);
    cudaGetSymbolAddress((void**)&ath, g_ath); cudaGetSymbolAddress((void**)&atl, g_atl);

    cudaFuncSetAttribute(gemm_bf3, cudaFuncAttributeMaxDynamicSharedMemorySize,
                         GEMM_SMEM);

    // split the 3 activation inputs (4M el each)
    Split4 sa;
    sa.s[0] = query; sa.h[0] = i0h; sa.l[0] = i0l;
    sa.s[1] = key;   sa.h[1] = i1h; sa.l[1] = i1l;
    sa.s[2] = value; sa.h[2] = i2h; sa.l[2] = i2l;
    sa.s[3] = query; sa.h[3] = i0h; sa.l[3] = i0l;  // unused
    splitk<<<dim3(NTOK*DIM/1024, 1, 3), 256>>>(sa);

    // split the 4 weights (1M el each)
    Split4 sw;
    sw.s[0] = Wq; sw.h[0] = w0h; sw.l[0] = w0l;
    sw.s[1] = Wk; sw.h[1] = w1h; sw.l[1] = w1l;
    sw.s[2] = Wv; sw.h[2] = w2h; sw.l[2] = w2l;
    sw.s[3] = Wo; sw.h[3] = w3h; sw.l[3] = w3l;
    splitk<<<dim3(DIM*DIM/1024, 1, 4), 256>>>(sw);

    // fused Q/K/V projections
    GemmArgs gqkv;
    gqkv.ah[0]=i0h; gqkv.al[0]=i0l; gqkv.wh[0]=w0h; gqkv.wl[0]=w0l; gqkv.bias[0]=bq; gqkv.c[0]=gq;
    gqkv.ah[1]=i1h; gqkv.al[1]=i1l; gqkv.wh[1]=w1h; gqkv.wl[1]=w1l; gqkv.bias[1]=bk; gqkv.c[1]=gk;
    gqkv.ah[2]=i2h; gqkv.al[2]=i2l; gqkv.wh[2]=w2h; gqkv.wl[2]=w2l; gqkv.bias[2]=bv; gqkv.c[2]=gv;
    gemm_bf3<<<dim3(DIM/128, NTOK/128, 3), 256, GEMM_SMEM>>>(gqkv);

    // attention (emits bf16 hi/lo)
    flash_attn<<<dim3(SEQ/64, BTCH*NH), 256>>>(gq, gk, gv, ath, atl);

    // output projection
    GemmArgs go;
    go.ah[0]=ath; go.al[0]=atl; go.wh[0]=w3h; go.wl[0]=w3l; go.bias[0]=bo; go.c[0]=out;
    go.ah[1]=ath; go.al[1]=atl; go.wh[1]=w3h; go.wl[1]=w3l; go.bias[1]=bo; go.c[1]=out;
    go.ah[2]=ath; go.al[2]=atl; go.wh[2]=w3h; go.wl[2]=w3l; go.bias[2]=bo; go.c[2]=out;
    gemm_bf3<<<dim3(DIM/128, NTOK/128, 1), 256, GEMM_SMEM>>>(go);
}